// round 16
// baseline (speedup 1.0000x reference)
#include <cuda_runtime.h>
#include <cuda_bf16.h>

#define N_NODE 100000
#define NEDGE  1600000
#define HID    128
#define OUTD   64

typedef unsigned long long ull;

// ---------------- scratch (device globals: allocation-free) ----------------
__device__ float d_agg_wu[N_NODE * 4];
__device__ float d_deg_wu[N_NODE];
__device__ float d_agg_uu[N_NODE * 16];   // stores MEAN directly
__device__ float d_h[N_NODE * HID];       // h_user pre-BN
__device__ float d_xp[N_NODE * HID];      // GAT projected features
__device__ float d_als[N_NODE * 4];
__device__ float d_ald[N_NODE * 4];
__device__ float d_gat[N_NODE * HID];     // GAT output (post bias+relu)
__device__ float d_stats[1024];
// stats: [0:128) sum1 [128:256) sq1 [256:384) sum2 [384:512) sq2
//        [512:640) scale1 [640:768) shift1 [768:896) scale2 [896:1024) shift2

// CSR for ei_uu grouped by dst
__device__ int d_cnt[N_NODE];
__device__ int d_rowptr[N_NODE + 2];
__device__ int d_cur[N_NODE];
__device__ int d_ssrc[NEDGE];
__device__ int d_part[128];

// ---------------- f32x2 packed helpers ----------------
__device__ __forceinline__ ull ffma2(ull a, ull b, ull c) {
    ull d;
    asm("fma.rn.f32x2 %0, %1, %2, %3;" : "=l"(d) : "l"(a), "l"(b), "l"(c));
    return d;
}
__device__ __forceinline__ ull pack2f(float x, float y) {
    ull r; asm("mov.b64 %0, {%1, %2};" : "=l"(r) : "f"(x), "f"(y)); return r;
}
__device__ __forceinline__ float sum2f(ull v) {
    float a, b; asm("mov.b64 {%0, %1}, %2;" : "=f"(a), "=f"(b) : "l"(v));
    return a + b;
}
__device__ __forceinline__ void red_add_v4(float* p, float4 v) {
    asm volatile("red.global.add.v4.f32 [%0], {%1,%2,%3,%4};"
                 :: "l"(p), "f"(v.x), "f"(v.y), "f"(v.z), "f"(v.w) : "memory");
}

// ---------------- init ----------------
__global__ void k_zero() {
    int i = blockIdx.x * blockDim.x + threadIdx.x;
    int st = gridDim.x * blockDim.x;
    for (int j = i; j < N_NODE; j += st) { d_cnt[j] = 0; d_deg_wu[j] = 0.f; }
    for (int j = i; j < N_NODE * 4; j += st) d_agg_wu[j] = 0.f;
    for (int j = i; j < 512; j += st) d_stats[j] = 0.f;
}

// Fused edge pass: ei_uu dst histogram (for CSR) + ei_wu feature scatter.
__global__ void k_edge_fused(const float* __restrict__ xw,
                             const int* __restrict__ ei_wu,
                             const int* __restrict__ ei_uu) {
    int e = blockIdx.x * blockDim.x + threadIdx.x;
    int st = gridDim.x * blockDim.x;
    for (; e < NEDGE; e += st) {
        atomicAdd(&d_cnt[__ldg(&ei_uu[NEDGE + e])], 1);
        int s = __ldg(&ei_wu[e]);
        int d = __ldg(&ei_wu[NEDGE + e]);
        float4 v = __ldg(((const float4*)xw) + s);
        red_add_v4(&d_agg_wu[d * 4], v);
        atomicAdd(&d_deg_wu[d], 1.0f);
    }
}

__global__ void k_scan1() { // 98 blocks x 256: per-block partial sums
    int b = blockIdx.x, t = threadIdx.x;
    int base = b * 1024 + t * 4;
    int s = 0;
    #pragma unroll
    for (int k = 0; k < 4; k++) { int i = base + k; if (i < N_NODE) s += d_cnt[i]; }
    __shared__ int sh[256];
    sh[t] = s; __syncthreads();
    for (int o = 128; o; o >>= 1) { if (t < o) sh[t] += sh[t + o]; __syncthreads(); }
    if (t == 0) d_part[b] = sh[0];
}

// block prefix computed inline
__global__ void k_scan3() { // 98 blocks x 256
    int b = blockIdx.x, t = threadIdx.x;
    __shared__ int shb[256];
    __shared__ int sh[256];
    __shared__ int s_base;
    int pv = (t < b) ? d_part[t] : 0;   // b <= 97 < 256
    shb[t] = pv; __syncthreads();
    for (int o = 128; o; o >>= 1) { if (t < o) shb[t] += shb[t + o]; __syncthreads(); }
    if (t == 0) s_base = shb[0];

    int base = b * 1024 + t * 4;
    int v[4];
    #pragma unroll
    for (int k = 0; k < 4; k++) { int i = base + k; v[k] = (i < N_NODE) ? d_cnt[i] : 0; }
    int tot = v[0] + v[1] + v[2] + v[3];
    __syncthreads();
    sh[t] = tot; __syncthreads();
    for (int o = 1; o < 256; o <<= 1) {
        int x = (t >= o) ? sh[t - o] : 0;
        __syncthreads();
        sh[t] += x;
        __syncthreads();
    }
    int baseOff = s_base + sh[t] - tot;
    int pref = 0;
    #pragma unroll
    for (int k = 0; k < 4; k++) {
        int i = base + k;
        if (i <= N_NODE) {
            d_rowptr[i] = baseOff + pref;
            if (i < N_NODE) d_cur[i] = baseOff + pref;
        }
        pref += v[k];
    }
}

// Scatter v2: 4 edges per thread, batched atomics (MLP 4), vectorized loads.
// Exactly-covering grid: 400000 threads handle 4 consecutive edges each.
__global__ void k_scatter(const int* __restrict__ ei) {
    int tid = blockIdx.x * blockDim.x + threadIdx.x;
    if (tid * 4 >= NEDGE) return;
    int4 sv = __ldg((const int4*)ei + tid);
    int4 dv = __ldg((const int4*)(ei + NEDGE) + tid);
    int p0 = atomicAdd(&d_cur[dv.x], 1);
    int p1 = atomicAdd(&d_cur[dv.y], 1);
    int p2 = atomicAdd(&d_cur[dv.z], 1);
    int p3 = atomicAdd(&d_cur[dv.w], 1);
    d_ssrc[p0] = sv.x;
    d_ssrc[p1] = sv.y;
    d_ssrc[p2] = sv.z;
    d_ssrc[p3] = sv.w;
}

// SAGE u2u mean aggregation via CSR: warp per dst
__global__ void __launch_bounds__(256) k_agg_uu(const float* __restrict__ xu) {
    int t = threadIdx.x, lane = t & 31;
    int warpId = (blockIdx.x * blockDim.x + t) >> 5;
    int nW = (gridDim.x * blockDim.x) >> 5;
    int half = lane >> 4, ch = lane & 15;
    for (int d = warpId; d < N_NODE; d += nW) {
        int start = d_rowptr[d], end = d_rowptr[d + 1];
        float acc = 0.f;
        for (int e = start + half; e < end; e += 2) {
            int s = __ldg(&d_ssrc[e]);
            acc += __ldg(&xu[s * 16 + ch]);
        }
        acc += __shfl_xor_sync(0xffffffffu, acc, 16);
        if (lane < 16) {
            float inv = 1.f / fmaxf((float)(end - start), 1.f);
            d_agg_uu[d * 16 + ch] = acc * inv;
        }
    }
}

// SAGE node phase v4: 8 rows/barrier pair, float4 shared reads.
__global__ void __launch_bounds__(128) k_sage_node(
    const float* __restrict__ xu,
    const float* __restrict__ wl1, const float* __restrict__ b1, const float* __restrict__ wr1,
    const float* __restrict__ wl2, const float* __restrict__ b2, const float* __restrict__ wr2)
{
    int c = threadIdx.x;
    float rwl1[4], rwr1[16], rwl2[16], rwr2[16];
    #pragma unroll
    for (int k = 0; k < 4; k++) rwl1[k] = __ldg(&wl1[k * 128 + c]);
    #pragma unroll
    for (int k = 0; k < 16; k++) {
        rwr1[k] = __ldg(&wr1[k * 128 + c]);
        rwl2[k] = __ldg(&wl2[k * 128 + c]);
        rwr2[k] = __ldg(&wr2[k * 128 + c]);
    }
    float rb1 = __ldg(&b1[c]), rb2 = __ldg(&b2[c]);
    __shared__ __align__(16) float s_in[8][36]; // 144B rows -> 16B-aligned chunks
    float lsum = 0.f, lsq = 0.f;
    for (int i0 = blockIdx.x * 8; i0 < N_NODE; i0 += gridDim.x * 8) {
        for (int j = c; j < 288; j += 128) {
            int r = j / 36, k = j - r * 36;
            int i = i0 + r;
            float v;
            if (k < 4)       v = d_agg_wu[i * 4 + k] / fmaxf(d_deg_wu[i], 1.f);
            else if (k < 20) v = __ldg(&xu[i * 16 + k - 4]);
            else             v = d_agg_uu[i * 16 + k - 20];
            s_in[r][k] = v;
        }
        __syncthreads();
        #pragma unroll
        for (int rr = 0; rr < 4; rr++) {
            const float* in0 = s_in[2 * rr];
            const float* in1 = s_in[2 * rr + 1];
            float a10 = rb1, a11 = rb1, a20 = rb2, a21 = rb2;
            {
                float4 u0 = *(const float4*)(in0);
                float4 u1 = *(const float4*)(in1);
                a10 = fmaf(u0.x, rwl1[0], a10); a11 = fmaf(u1.x, rwl1[0], a11);
                a10 = fmaf(u0.y, rwl1[1], a10); a11 = fmaf(u1.y, rwl1[1], a11);
                a10 = fmaf(u0.z, rwl1[2], a10); a11 = fmaf(u1.z, rwl1[2], a11);
                a10 = fmaf(u0.w, rwl1[3], a10); a11 = fmaf(u1.w, rwl1[3], a11);
            }
            #pragma unroll
            for (int q = 0; q < 4; q++) {
                float4 x0 = *(const float4*)(in0 + 4 + 4 * q);
                float4 x1 = *(const float4*)(in1 + 4 + 4 * q);
                float4 g0 = *(const float4*)(in0 + 20 + 4 * q);
                float4 g1 = *(const float4*)(in1 + 20 + 4 * q);
                const float* xe0 = (const float*)&x0;
                const float* xe1 = (const float*)&x1;
                const float* ge0 = (const float*)&g0;
                const float* ge1 = (const float*)&g1;
                #pragma unroll
                for (int e = 0; e < 4; e++) {
                    int k = 4 * q + e;
                    a10 = fmaf(xe0[e], rwr1[k], a10);
                    a11 = fmaf(xe1[e], rwr1[k], a11);
                    a20 = fmaf(xe0[e], rwr2[k], a20);
                    a21 = fmaf(xe1[e], rwr2[k], a21);
                    a20 = fmaf(ge0[e], rwl2[k], a20);
                    a21 = fmaf(ge1[e], rwl2[k], a21);
                }
            }
            float h0 = fmaxf(a10, 0.f) + fmaxf(a20, 0.f);
            float h1 = fmaxf(a11, 0.f) + fmaxf(a21, 0.f);
            d_h[(i0 + 2 * rr) * HID + c] = h0;
            d_h[(i0 + 2 * rr + 1) * HID + c] = h1;
            lsum += h0 + h1;
            lsq = fmaf(h0, h0, lsq);
            lsq = fmaf(h1, h1, lsq);
        }
        __syncthreads();
    }
    atomicAdd(&d_stats[c], lsum);
    atomicAdd(&d_stats[128 + c], lsq);
}

__global__ void k_bn_fin(const float* __restrict__ g, const float* __restrict__ b,
                         int sIn, int sOut) {
    int c = threadIdx.x;
    float invN = 1.0f / (float)N_NODE;
    float mean = d_stats[sIn + c] * invN;
    float var = d_stats[sIn + 128 + c] * invN - mean * mean;
    float sc = g[c] * rsqrtf(var + 1e-5f);
    d_stats[sOut + c] = sc;
    d_stats[sOut + 128 + c] = fmaf(-mean, sc, b[c]);
}

// xp = BN1(h) @ gat_w + attention logits.
// v4: 512 thr, 4-way k split, 8 rows/pair, 16B shared loads.
__global__ void __launch_bounds__(512) k_xp(
    const float* __restrict__ W, const float* __restrict__ a_src, const float* __restrict__ a_dst)
{
    __shared__ __align__(16) float sh[8][128];
    __shared__ float red[4][8][128];  // [kq][row][c]
    int t = threadIdx.x;
    int kq = t >> 7;        // 0..3
    int c = t & 127;
    int k0 = kq * 32;
    ull w[16];
    #pragma unroll
    for (int j = 0; j < 16; j++) {
        int ka = k0 + 2 * j;
        w[j] = pack2f(__ldg(&W[ka * 128 + c]), __ldg(&W[(ka + 1) * 128 + c]));
    }
    float scale = d_stats[512 + c];
    float shift = d_stats[640 + c];
    float asr = __ldg(&a_src[c]);
    float adr = __ldg(&a_dst[c]);
    int h = c >> 5;

    for (int i0 = blockIdx.x * 8; i0 < N_NODE; i0 += gridDim.x * 8) {
        sh[kq][c]     = fmaf(d_h[(i0 + kq) * HID + c], scale, shift);
        sh[kq + 4][c] = fmaf(d_h[(i0 + kq + 4) * HID + c], scale, shift);
        __syncthreads();
        ull a[8];
        #pragma unroll
        for (int r = 0; r < 8; r++) a[r] = 0ull;
        #pragma unroll
        for (int jj = 0; jj < 8; jj++) {
            #pragma unroll
            for (int r = 0; r < 8; r++) {
                ulonglong2 v = *(const ulonglong2*)&sh[r][k0 + 4 * jj];
                a[r] = ffma2(v.x, w[2 * jj], a[r]);
                a[r] = ffma2(v.y, w[2 * jj + 1], a[r]);
            }
        }
        #pragma unroll
        for (int r = 0; r < 8; r++) red[kq][r][c] = sum2f(a[r]);
        __syncthreads();
        #pragma unroll
        for (int rr = 0; rr < 2; rr++) {
            int r = kq + rr * 4;
            float xpv = red[0][r][c] + red[1][r][c] + red[2][r][c] + red[3][r][c];
            int ii = i0 + r;
            d_xp[ii * HID + c] = xpv;
            float vs = xpv * asr, vd = xpv * adr;
            #pragma unroll
            for (int o = 16; o > 0; o >>= 1) {
                vs += __shfl_xor_sync(0xffffffffu, vs, o);
                vd += __shfl_xor_sync(0xffffffffu, vd, o);
            }
            if ((c & 31) == 0) {
                d_als[ii * 4 + h] = vs;
                d_ald[ii * 4 + h] = vd;
            }
        }
    }
}

// GAT via CSR: warp per dst; fused softmax + bias + relu + BN2 stats
__global__ void __launch_bounds__(256) k_gat_csr(const float* __restrict__ gat_b) {
    __shared__ float s_sum[128], s_sq[128];
    int t = threadIdx.x, lane = t & 31, w = t >> 5;
    if (t < 128) { s_sum[t] = 0.f; s_sq[t] = 0.f; }
    __syncthreads();
    int c4 = lane * 4, h = lane >> 3;
    float4 bias = __ldg((const float4*)&gat_b[c4]);
    float4 lsum = {0, 0, 0, 0}, lsq = {0, 0, 0, 0};
    int warpId = blockIdx.x * 8 + w;
    int nW = gridDim.x * 8;
    for (int d = warpId; d < N_NODE; d += nW) {
        int start = d_rowptr[d], end = d_rowptr[d + 1];
        float ald_h = __ldg(&d_ald[d * 4 + h]);
        float denom = 0.f;
        float4 acc = {0, 0, 0, 0};
        for (int e = start; e <= end; e++) {
            int s = (e < end) ? __ldg(&d_ssrc[e]) : d;   // final iter = self-loop
            float l = __ldg(&d_als[s * 4 + h]) + ald_h;
            l = l > 0.f ? l : 0.2f * l;
            float wt = __expf(l);
            denom += wt;
            float4 xv = __ldg((const float4*)&d_xp[s * HID + c4]);
            acc.x = fmaf(wt, xv.x, acc.x);
            acc.y = fmaf(wt, xv.y, acc.y);
            acc.z = fmaf(wt, xv.z, acc.z);
            acc.w = fmaf(wt, xv.w, acc.w);
        }
        float inv = 1.f / (denom + 1e-16f);
        float4 g;
        g.x = fmaxf(fmaf(acc.x, inv, bias.x), 0.f);
        g.y = fmaxf(fmaf(acc.y, inv, bias.y), 0.f);
        g.z = fmaxf(fmaf(acc.z, inv, bias.z), 0.f);
        g.w = fmaxf(fmaf(acc.w, inv, bias.w), 0.f);
        *(float4*)&d_gat[d * HID + c4] = g;
        lsum.x += g.x; lsum.y += g.y; lsum.z += g.z; lsum.w += g.w;
        lsq.x = fmaf(g.x, g.x, lsq.x);
        lsq.y = fmaf(g.y, g.y, lsq.y);
        lsq.z = fmaf(g.z, g.z, lsq.z);
        lsq.w = fmaf(g.w, g.w, lsq.w);
    }
    atomicAdd(&s_sum[c4 + 0], lsum.x); atomicAdd(&s_sq[c4 + 0], lsq.x);
    atomicAdd(&s_sum[c4 + 1], lsum.y); atomicAdd(&s_sq[c4 + 1], lsq.y);
    atomicAdd(&s_sum[c4 + 2], lsum.z); atomicAdd(&s_sq[c4 + 2], lsq.z);
    atomicAdd(&s_sum[c4 + 3], lsum.w); atomicAdd(&s_sq[c4 + 3], lsq.w);
    __syncthreads();
    if (t < 128) {
        atomicAdd(&d_stats[256 + t], s_sum[t]);
        atomicAdd(&d_stats[384 + t], s_sq[t]);
    }
}

// out = relu(BN2(g) @ proj_w + proj_b); v3: 16B shared loads.
__global__ void __launch_bounds__(256) k_proj(
    const float* __restrict__ PW, const float* __restrict__ pb, float* __restrict__ out)
{
    __shared__ __align__(16) float sh[4][128];
    __shared__ float red[4][4][64];  // [kq][row][o]
    int t = threadIdx.x;
    int kq = t >> 6;        // 0..3
    int o = t & 63;
    int k0 = kq * 32;
    ull w[16];
    #pragma unroll
    for (int j = 0; j < 16; j++) {
        int ka = k0 + 2 * j;
        w[j] = pack2f(__ldg(&PW[ka * 64 + o]), __ldg(&PW[(ka + 1) * 64 + o]));
    }
    int cs = t & 127;       // staging column
    int r0 = t >> 7;        // staging row 0..1
    float scale = d_stats[768 + cs];
    float shift = d_stats[896 + cs];
    float pbias = __ldg(&pb[o]);

    for (int i0 = blockIdx.x * 4; i0 < N_NODE; i0 += gridDim.x * 4) {
        sh[r0][cs]     = fmaf(d_gat[(i0 + r0) * HID + cs], scale, shift);
        sh[r0 + 2][cs] = fmaf(d_gat[(i0 + r0 + 2) * HID + cs], scale, shift);
        __syncthreads();
        ull a0 = 0ull, a1 = 0ull, a2 = 0ull, a3 = 0ull;
        #pragma unroll
        for (int jj = 0; jj < 8; jj++) {
            ulonglong2 v0 = *(const ulonglong2*)&sh[0][k0 + 4 * jj];
            ulonglong2 v1 = *(const ulonglong2*)&sh[1][k0 + 4 * jj];
            ulonglong2 v2 = *(const ulonglong2*)&sh[2][k0 + 4 * jj];
            ulonglong2 v3 = *(const ulonglong2*)&sh[3][k0 + 4 * jj];
            ull wa = w[2 * jj], wb = w[2 * jj + 1];
            a0 = ffma2(v0.x, wa, a0); a0 = ffma2(v0.y, wb, a0);
            a1 = ffma2(v1.x, wa, a1); a1 = ffma2(v1.y, wb, a1);
            a2 = ffma2(v2.x, wa, a2); a2 = ffma2(v2.y, wb, a2);
            a3 = ffma2(v3.x, wa, a3); a3 = ffma2(v3.y, wb, a3);
        }
        red[kq][0][o] = sum2f(a0);
        red[kq][1][o] = sum2f(a1);
        red[kq][2][o] = sum2f(a2);
        red[kq][3][o] = sum2f(a3);
        __syncthreads();
        {
            int r = kq;
            float v = red[0][r][o] + red[1][r][o] + red[2][r][o] + red[3][r][o] + pbias;
            out[(i0 + r) * OUTD + o] = fmaxf(v, 0.f);
        }
    }
}

// ---------------- launch ----------------
extern "C" void kernel_launch(void* const* d_in, const int* in_sizes, int n_in,
                              void* d_out, int out_size) {
    const float* x_user   = (const float*)d_in[0];
    const float* x_wallet = (const float*)d_in[1];
    const float* w_w2u_l = (const float*)d_in[5];
    const float* b_w2u   = (const float*)d_in[6];
    const float* w_w2u_r = (const float*)d_in[7];
    const float* w_u2u_l = (const float*)d_in[8];
    const float* b_u2u   = (const float*)d_in[9];
    const float* w_u2u_r = (const float*)d_in[10];
    const float* bn_u_g  = (const float*)d_in[11];
    const float* bn_u_b  = (const float*)d_in[12];
    const float* gat_w  = (const float*)d_in[15];
    const float* gat_as = (const float*)d_in[16];
    const float* gat_ad = (const float*)d_in[17];
    const float* gat_b  = (const float*)d_in[18];
    const float* bn2_g  = (const float*)d_in[19];
    const float* bn2_b  = (const float*)d_in[20];
    const float* proj_w = (const float*)d_in[21];
    const float* proj_b = (const float*)d_in[22];
    const int* ei_wu = (const int*)d_in[24];
    const int* ei_uu = (const int*)d_in[25];
    float* out = (float*)d_out;

    k_zero<<<512, 256>>>();                              // 0
    k_edge_fused<<<2048, 256>>>(x_wallet, ei_wu, ei_uu); // 1
    k_scan1<<<98, 256>>>();                              // 2
    k_scan3<<<98, 256>>>();                              // 3
    k_scatter<<<1563, 256>>>(ei_uu);                     // 4 (4 edges/thread, MLP 4)
    k_agg_uu<<<1024, 256>>>(x_user);                     // 5
    k_sage_node<<<1184, 128>>>(x_user, w_w2u_l, b_w2u, w_w2u_r, w_u2u_l, b_u2u, w_u2u_r); // 6
    k_bn_fin<<<1, 128>>>(bn_u_g, bn_u_b, 0, 512);        // 7
    k_xp<<<1024, 512>>>(gat_w, gat_as, gat_ad);          // 8
    k_gat_csr<<<1024, 256>>>(gat_b);                     // 9
    k_bn_fin<<<1, 128>>>(bn2_g, bn2_b, 256, 768);        // 10
    k_proj<<<1024, 256>>>(proj_w, proj_b, out);          // 11
}

// round 17
// speedup vs baseline: 1.0489x; 1.0489x over previous
#include <cuda_runtime.h>
#include <cuda_bf16.h>

#define N_NODE 100000
#define NEDGE  1600000
#define HID    128
#define OUTD   64

typedef unsigned long long ull;

// ---------------- scratch (device globals: allocation-free) ----------------
__device__ float d_agg_wu[N_NODE * 4];
__device__ float d_deg_wu[N_NODE];
__device__ float d_agg_uu[N_NODE * 16];   // stores MEAN directly
__device__ float d_h[N_NODE * HID];       // h_user pre-BN
__device__ float d_xp[N_NODE * HID];      // GAT projected features
__device__ float d_als[N_NODE * 4];
__device__ float d_ald[N_NODE * 4];
__device__ float d_gat[N_NODE * HID];     // GAT output (post bias+relu)
__device__ float d_stats[1024];
// stats: [0:128) sum1 [128:256) sq1 [256:384) sum2 [384:512) sq2
//        [512:640) scale1 [640:768) shift1 [768:896) scale2 [896:1024) shift2

// CSR for ei_uu grouped by dst
__device__ int d_cnt[N_NODE];
__device__ int d_rowptr[N_NODE + 2];
__device__ int d_cur[N_NODE];
__device__ int d_ssrc[NEDGE];
__device__ int d_part[128];

// ---------------- f32x2 packed helpers ----------------
__device__ __forceinline__ ull ffma2(ull a, ull b, ull c) {
    ull d;
    asm("fma.rn.f32x2 %0, %1, %2, %3;" : "=l"(d) : "l"(a), "l"(b), "l"(c));
    return d;
}
__device__ __forceinline__ ull pack2f(float x, float y) {
    ull r; asm("mov.b64 %0, {%1, %2};" : "=l"(r) : "f"(x), "f"(y)); return r;
}
__device__ __forceinline__ float sum2f(ull v) {
    float a, b; asm("mov.b64 {%0, %1}, %2;" : "=f"(a), "=f"(b) : "l"(v));
    return a + b;
}
__device__ __forceinline__ void red_add_v4(float* p, float4 v) {
    asm volatile("red.global.add.v4.f32 [%0], {%1,%2,%3,%4};"
                 :: "l"(p), "f"(v.x), "f"(v.y), "f"(v.z), "f"(v.w) : "memory");
}

// ---------------- init ----------------
__global__ void k_zero() {
    int i = blockIdx.x * blockDim.x + threadIdx.x;
    int st = gridDim.x * blockDim.x;
    for (int j = i; j < N_NODE; j += st) { d_cnt[j] = 0; d_deg_wu[j] = 0.f; }
    for (int j = i; j < N_NODE * 4; j += st) d_agg_wu[j] = 0.f;
    for (int j = i; j < 512; j += st) d_stats[j] = 0.f;
}

// Fused edge pass: ei_uu dst histogram (for CSR) + ei_wu feature scatter.
__global__ void k_edge_fused(const float* __restrict__ xw,
                             const int* __restrict__ ei_wu,
                             const int* __restrict__ ei_uu) {
    int e = blockIdx.x * blockDim.x + threadIdx.x;
    int st = gridDim.x * blockDim.x;
    for (; e < NEDGE; e += st) {
        atomicAdd(&d_cnt[__ldg(&ei_uu[NEDGE + e])], 1);
        int s = __ldg(&ei_wu[e]);
        int d = __ldg(&ei_wu[NEDGE + e]);
        float4 v = __ldg(((const float4*)xw) + s);
        red_add_v4(&d_agg_wu[d * 4], v);
        atomicAdd(&d_deg_wu[d], 1.0f);
    }
}

__global__ void k_scan1() { // 98 blocks x 256: per-block partial sums
    int b = blockIdx.x, t = threadIdx.x;
    int base = b * 1024 + t * 4;
    int s = 0;
    #pragma unroll
    for (int k = 0; k < 4; k++) { int i = base + k; if (i < N_NODE) s += d_cnt[i]; }
    __shared__ int sh[256];
    sh[t] = s; __syncthreads();
    for (int o = 128; o; o >>= 1) { if (t < o) sh[t] += sh[t + o]; __syncthreads(); }
    if (t == 0) d_part[b] = sh[0];
}

// block prefix computed inline
__global__ void k_scan3() { // 98 blocks x 256
    int b = blockIdx.x, t = threadIdx.x;
    __shared__ int shb[256];
    __shared__ int sh[256];
    __shared__ int s_base;
    int pv = (t < b) ? d_part[t] : 0;   // b <= 97 < 256
    shb[t] = pv; __syncthreads();
    for (int o = 128; o; o >>= 1) { if (t < o) shb[t] += shb[t + o]; __syncthreads(); }
    if (t == 0) s_base = shb[0];

    int base = b * 1024 + t * 4;
    int v[4];
    #pragma unroll
    for (int k = 0; k < 4; k++) { int i = base + k; v[k] = (i < N_NODE) ? d_cnt[i] : 0; }
    int tot = v[0] + v[1] + v[2] + v[3];
    __syncthreads();
    sh[t] = tot; __syncthreads();
    for (int o = 1; o < 256; o <<= 1) {
        int x = (t >= o) ? sh[t - o] : 0;
        __syncthreads();
        sh[t] += x;
        __syncthreads();
    }
    int baseOff = s_base + sh[t] - tot;
    int pref = 0;
    #pragma unroll
    for (int k = 0; k < 4; k++) {
        int i = base + k;
        if (i <= N_NODE) {
            d_rowptr[i] = baseOff + pref;
            if (i < N_NODE) d_cur[i] = baseOff + pref;
        }
        pref += v[k];
    }
}

// Scatter v1 (batched v2 regressed — reverted): grid-stride, 1 edge/iter.
__global__ void k_scatter(const int* __restrict__ ei) {
    int e = blockIdx.x * blockDim.x + threadIdx.x;
    int st = gridDim.x * blockDim.x;
    for (; e < NEDGE; e += st) {
        int s = __ldg(&ei[e]);
        int d = __ldg(&ei[NEDGE + e]);
        int p = atomicAdd(&d_cur[d], 1);
        d_ssrc[p] = s;
    }
}

// SAGE u2u mean aggregation via CSR: warp per dst
__global__ void __launch_bounds__(256) k_agg_uu(const float* __restrict__ xu) {
    int t = threadIdx.x, lane = t & 31;
    int warpId = (blockIdx.x * blockDim.x + t) >> 5;
    int nW = (gridDim.x * blockDim.x) >> 5;
    int half = lane >> 4, ch = lane & 15;
    for (int d = warpId; d < N_NODE; d += nW) {
        int start = d_rowptr[d], end = d_rowptr[d + 1];
        float acc = 0.f;
        for (int e = start + half; e < end; e += 2) {
            int s = __ldg(&d_ssrc[e]);
            acc += __ldg(&xu[s * 16 + ch]);
        }
        acc += __shfl_xor_sync(0xffffffffu, acc, 16);
        if (lane < 16) {
            float inv = 1.f / fmaxf((float)(end - start), 1.f);
            d_agg_uu[d * 16 + ch] = acc * inv;
        }
    }
}

// SAGE node phase v5: v4 compute body (8 rows/pair, float4 shared reads) with
// vectorized branch-partitioned staging (72 float4 loads, no int division).
__global__ void __launch_bounds__(128) k_sage_node(
    const float* __restrict__ xu,
    const float* __restrict__ wl1, const float* __restrict__ b1, const float* __restrict__ wr1,
    const float* __restrict__ wl2, const float* __restrict__ b2, const float* __restrict__ wr2)
{
    int c = threadIdx.x;
    float rwl1[4], rwr1[16], rwl2[16], rwr2[16];
    #pragma unroll
    for (int k = 0; k < 4; k++) rwl1[k] = __ldg(&wl1[k * 128 + c]);
    #pragma unroll
    for (int k = 0; k < 16; k++) {
        rwr1[k] = __ldg(&wr1[k * 128 + c]);
        rwl2[k] = __ldg(&wl2[k * 128 + c]);
        rwr2[k] = __ldg(&wr2[k * 128 + c]);
    }
    float rb1 = __ldg(&b1[c]), rb2 = __ldg(&b2[c]);
    __shared__ __align__(16) float s_in[8][36]; // 144B rows -> 16B-aligned chunks
    float lsum = 0.f, lsq = 0.f;
    for (int i0 = blockIdx.x * 8; i0 < N_NODE; i0 += gridDim.x * 8) {
        // vectorized staging: threads 0-7 agg_wu(+deg), 8-39 xu, 40-71 agg_uu
        if (c < 8) {
            int i = i0 + c;
            float4 v = *(const float4*)&d_agg_wu[i * 4];
            float inv = 1.f / fmaxf(d_deg_wu[i], 1.f);
            v.x *= inv; v.y *= inv; v.z *= inv; v.w *= inv;
            *(float4*)&s_in[c][0] = v;
        } else if (c < 40) {
            int j = c - 8, r = j >> 2, q = j & 3;
            *(float4*)&s_in[r][4 + 4 * q] = __ldg((const float4*)&xu[(i0 + r) * 16 + 4 * q]);
        } else if (c < 72) {
            int j = c - 40, r = j >> 2, q = j & 3;
            *(float4*)&s_in[r][20 + 4 * q] = *(const float4*)&d_agg_uu[(i0 + r) * 16 + 4 * q];
        }
        __syncthreads();
        #pragma unroll
        for (int rr = 0; rr < 4; rr++) {
            const float* in0 = s_in[2 * rr];
            const float* in1 = s_in[2 * rr + 1];
            float a10 = rb1, a11 = rb1, a20 = rb2, a21 = rb2;
            {
                float4 u0 = *(const float4*)(in0);
                float4 u1 = *(const float4*)(in1);
                a10 = fmaf(u0.x, rwl1[0], a10); a11 = fmaf(u1.x, rwl1[0], a11);
                a10 = fmaf(u0.y, rwl1[1], a10); a11 = fmaf(u1.y, rwl1[1], a11);
                a10 = fmaf(u0.z, rwl1[2], a10); a11 = fmaf(u1.z, rwl1[2], a11);
                a10 = fmaf(u0.w, rwl1[3], a10); a11 = fmaf(u1.w, rwl1[3], a11);
            }
            #pragma unroll
            for (int q = 0; q < 4; q++) {
                float4 x0 = *(const float4*)(in0 + 4 + 4 * q);
                float4 x1 = *(const float4*)(in1 + 4 + 4 * q);
                float4 g0 = *(const float4*)(in0 + 20 + 4 * q);
                float4 g1 = *(const float4*)(in1 + 20 + 4 * q);
                const float* xe0 = (const float*)&x0;
                const float* xe1 = (const float*)&x1;
                const float* ge0 = (const float*)&g0;
                const float* ge1 = (const float*)&g1;
                #pragma unroll
                for (int e = 0; e < 4; e++) {
                    int k = 4 * q + e;
                    a10 = fmaf(xe0[e], rwr1[k], a10);
                    a11 = fmaf(xe1[e], rwr1[k], a11);
                    a20 = fmaf(xe0[e], rwr2[k], a20);
                    a21 = fmaf(xe1[e], rwr2[k], a21);
                    a20 = fmaf(ge0[e], rwl2[k], a20);
                    a21 = fmaf(ge1[e], rwl2[k], a21);
                }
            }
            float h0 = fmaxf(a10, 0.f) + fmaxf(a20, 0.f);
            float h1 = fmaxf(a11, 0.f) + fmaxf(a21, 0.f);
            d_h[(i0 + 2 * rr) * HID + c] = h0;
            d_h[(i0 + 2 * rr + 1) * HID + c] = h1;
            lsum += h0 + h1;
            lsq = fmaf(h0, h0, lsq);
            lsq = fmaf(h1, h1, lsq);
        }
        __syncthreads();
    }
    atomicAdd(&d_stats[c], lsum);
    atomicAdd(&d_stats[128 + c], lsq);
}

__global__ void k_bn_fin(const float* __restrict__ g, const float* __restrict__ b,
                         int sIn, int sOut) {
    int c = threadIdx.x;
    float invN = 1.0f / (float)N_NODE;
    float mean = d_stats[sIn + c] * invN;
    float var = d_stats[sIn + 128 + c] * invN - mean * mean;
    float sc = g[c] * rsqrtf(var + 1e-5f);
    d_stats[sOut + c] = sc;
    d_stats[sOut + 128 + c] = fmaf(-mean, sc, b[c]);
}

// xp = BN1(h) @ gat_w + attention logits.
// v4: 512 thr, 4-way k split, 8 rows/pair, 16B shared loads.
__global__ void __launch_bounds__(512) k_xp(
    const float* __restrict__ W, const float* __restrict__ a_src, const float* __restrict__ a_dst)
{
    __shared__ __align__(16) float sh[8][128];
    __shared__ float red[4][8][128];  // [kq][row][c]
    int t = threadIdx.x;
    int kq = t >> 7;        // 0..3
    int c = t & 127;
    int k0 = kq * 32;
    ull w[16];
    #pragma unroll
    for (int j = 0; j < 16; j++) {
        int ka = k0 + 2 * j;
        w[j] = pack2f(__ldg(&W[ka * 128 + c]), __ldg(&W[(ka + 1) * 128 + c]));
    }
    float scale = d_stats[512 + c];
    float shift = d_stats[640 + c];
    float asr = __ldg(&a_src[c]);
    float adr = __ldg(&a_dst[c]);
    int h = c >> 5;

    for (int i0 = blockIdx.x * 8; i0 < N_NODE; i0 += gridDim.x * 8) {
        sh[kq][c]     = fmaf(d_h[(i0 + kq) * HID + c], scale, shift);
        sh[kq + 4][c] = fmaf(d_h[(i0 + kq + 4) * HID + c], scale, shift);
        __syncthreads();
        ull a[8];
        #pragma unroll
        for (int r = 0; r < 8; r++) a[r] = 0ull;
        #pragma unroll
        for (int jj = 0; jj < 8; jj++) {
            #pragma unroll
            for (int r = 0; r < 8; r++) {
                ulonglong2 v = *(const ulonglong2*)&sh[r][k0 + 4 * jj];
                a[r] = ffma2(v.x, w[2 * jj], a[r]);
                a[r] = ffma2(v.y, w[2 * jj + 1], a[r]);
            }
        }
        #pragma unroll
        for (int r = 0; r < 8; r++) red[kq][r][c] = sum2f(a[r]);
        __syncthreads();
        #pragma unroll
        for (int rr = 0; rr < 2; rr++) {
            int r = kq + rr * 4;
            float xpv = red[0][r][c] + red[1][r][c] + red[2][r][c] + red[3][r][c];
            int ii = i0 + r;
            d_xp[ii * HID + c] = xpv;
            float vs = xpv * asr, vd = xpv * adr;
            #pragma unroll
            for (int o = 16; o > 0; o >>= 1) {
                vs += __shfl_xor_sync(0xffffffffu, vs, o);
                vd += __shfl_xor_sync(0xffffffffu, vd, o);
            }
            if ((c & 31) == 0) {
                d_als[ii * 4 + h] = vs;
                d_ald[ii * 4 + h] = vd;
            }
        }
    }
}

// GAT via CSR: warp per dst; fused softmax + bias + relu + BN2 stats
__global__ void __launch_bounds__(256) k_gat_csr(const float* __restrict__ gat_b) {
    __shared__ float s_sum[128], s_sq[128];
    int t = threadIdx.x, lane = t & 31, w = t >> 5;
    if (t < 128) { s_sum[t] = 0.f; s_sq[t] = 0.f; }
    __syncthreads();
    int c4 = lane * 4, h = lane >> 3;
    float4 bias = __ldg((const float4*)&gat_b[c4]);
    float4 lsum = {0, 0, 0, 0}, lsq = {0, 0, 0, 0};
    int warpId = blockIdx.x * 8 + w;
    int nW = gridDim.x * 8;
    for (int d = warpId; d < N_NODE; d += nW) {
        int start = d_rowptr[d], end = d_rowptr[d + 1];
        float ald_h = __ldg(&d_ald[d * 4 + h]);
        float denom = 0.f;
        float4 acc = {0, 0, 0, 0};
        for (int e = start; e <= end; e++) {
            int s = (e < end) ? __ldg(&d_ssrc[e]) : d;   // final iter = self-loop
            float l = __ldg(&d_als[s * 4 + h]) + ald_h;
            l = l > 0.f ? l : 0.2f * l;
            float wt = __expf(l);
            denom += wt;
            float4 xv = __ldg((const float4*)&d_xp[s * HID + c4]);
            acc.x = fmaf(wt, xv.x, acc.x);
            acc.y = fmaf(wt, xv.y, acc.y);
            acc.z = fmaf(wt, xv.z, acc.z);
            acc.w = fmaf(wt, xv.w, acc.w);
        }
        float inv = 1.f / (denom + 1e-16f);
        float4 g;
        g.x = fmaxf(fmaf(acc.x, inv, bias.x), 0.f);
        g.y = fmaxf(fmaf(acc.y, inv, bias.y), 0.f);
        g.z = fmaxf(fmaf(acc.z, inv, bias.z), 0.f);
        g.w = fmaxf(fmaf(acc.w, inv, bias.w), 0.f);
        *(float4*)&d_gat[d * HID + c4] = g;
        lsum.x += g.x; lsum.y += g.y; lsum.z += g.z; lsum.w += g.w;
        lsq.x = fmaf(g.x, g.x, lsq.x);
        lsq.y = fmaf(g.y, g.y, lsq.y);
        lsq.z = fmaf(g.z, g.z, lsq.z);
        lsq.w = fmaf(g.w, g.w, lsq.w);
    }
    atomicAdd(&s_sum[c4 + 0], lsum.x); atomicAdd(&s_sq[c4 + 0], lsq.x);
    atomicAdd(&s_sum[c4 + 1], lsum.y); atomicAdd(&s_sq[c4 + 1], lsq.y);
    atomicAdd(&s_sum[c4 + 2], lsum.z); atomicAdd(&s_sq[c4 + 2], lsq.z);
    atomicAdd(&s_sum[c4 + 3], lsum.w); atomicAdd(&s_sq[c4 + 3], lsq.w);
    __syncthreads();
    if (t < 128) {
        atomicAdd(&d_stats[256 + t], s_sum[t]);
        atomicAdd(&d_stats[384 + t], s_sq[t]);
    }
}

// out = relu(BN2(g) @ proj_w + proj_b); v3: 16B shared loads.
__global__ void __launch_bounds__(256) k_proj(
    const float* __restrict__ PW, const float* __restrict__ pb, float* __restrict__ out)
{
    __shared__ __align__(16) float sh[4][128];
    __shared__ float red[4][4][64];  // [kq][row][o]
    int t = threadIdx.x;
    int kq = t >> 6;        // 0..3
    int o = t & 63;
    int k0 = kq * 32;
    ull w[16];
    #pragma unroll
    for (int j = 0; j < 16; j++) {
        int ka = k0 + 2 * j;
        w[j] = pack2f(__ldg(&PW[ka * 64 + o]), __ldg(&PW[(ka + 1) * 64 + o]));
    }
    int cs = t & 127;       // staging column
    int r0 = t >> 7;        // staging row 0..1
    float scale = d_stats[768 + cs];
    float shift = d_stats[896 + cs];
    float pbias = __ldg(&pb[o]);

    for (int i0 = blockIdx.x * 4; i0 < N_NODE; i0 += gridDim.x * 4) {
        sh[r0][cs]     = fmaf(d_gat[(i0 + r0) * HID + cs], scale, shift);
        sh[r0 + 2][cs] = fmaf(d_gat[(i0 + r0 + 2) * HID + cs], scale, shift);
        __syncthreads();
        ull a0 = 0ull, a1 = 0ull, a2 = 0ull, a3 = 0ull;
        #pragma unroll
        for (int jj = 0; jj < 8; jj++) {
            ulonglong2 v0 = *(const ulonglong2*)&sh[0][k0 + 4 * jj];
            ulonglong2 v1 = *(const ulonglong2*)&sh[1][k0 + 4 * jj];
            ulonglong2 v2 = *(const ulonglong2*)&sh[2][k0 + 4 * jj];
            ulonglong2 v3 = *(const ulonglong2*)&sh[3][k0 + 4 * jj];
            ull wa = w[2 * jj], wb = w[2 * jj + 1];
            a0 = ffma2(v0.x, wa, a0); a0 = ffma2(v0.y, wb, a0);
            a1 = ffma2(v1.x, wa, a1); a1 = ffma2(v1.y, wb, a1);
            a2 = ffma2(v2.x, wa, a2); a2 = ffma2(v2.y, wb, a2);
            a3 = ffma2(v3.x, wa, a3); a3 = ffma2(v3.y, wb, a3);
        }
        red[kq][0][o] = sum2f(a0);
        red[kq][1][o] = sum2f(a1);
        red[kq][2][o] = sum2f(a2);
        red[kq][3][o] = sum2f(a3);
        __syncthreads();
        {
            int r = kq;
            float v = red[0][r][o] + red[1][r][o] + red[2][r][o] + red[3][r][o] + pbias;
            out[(i0 + r) * OUTD + o] = fmaxf(v, 0.f);
        }
    }
}

// ---------------- launch ----------------
extern "C" void kernel_launch(void* const* d_in, const int* in_sizes, int n_in,
                              void* d_out, int out_size) {
    const float* x_user   = (const float*)d_in[0];
    const float* x_wallet = (const float*)d_in[1];
    const float* w_w2u_l = (const float*)d_in[5];
    const float* b_w2u   = (const float*)d_in[6];
    const float* w_w2u_r = (const float*)d_in[7];
    const float* w_u2u_l = (const float*)d_in[8];
    const float* b_u2u   = (const float*)d_in[9];
    const float* w_u2u_r = (const float*)d_in[10];
    const float* bn_u_g  = (const float*)d_in[11];
    const float* bn_u_b  = (const float*)d_in[12];
    const float* gat_w  = (const float*)d_in[15];
    const float* gat_as = (const float*)d_in[16];
    const float* gat_ad = (const float*)d_in[17];
    const float* gat_b  = (const float*)d_in[18];
    const float* bn2_g  = (const float*)d_in[19];
    const float* bn2_b  = (const float*)d_in[20];
    const float* proj_w = (const float*)d_in[21];
    const float* proj_b = (const float*)d_in[22];
    const int* ei_wu = (const int*)d_in[24];
    const int* ei_uu = (const int*)d_in[25];
    float* out = (float*)d_out;

    k_zero<<<512, 256>>>();                              // 0
    k_edge_fused<<<2048, 256>>>(x_wallet, ei_wu, ei_uu); // 1
    k_scan1<<<98, 256>>>();                              // 2
    k_scan3<<<98, 256>>>();                              // 3
    k_scatter<<<2048, 256>>>(ei_uu);                     // 4
    k_agg_uu<<<1024, 256>>>(x_user);                     // 5
    k_sage_node<<<1184, 128>>>(x_user, w_w2u_l, b_w2u, w_w2u_r, w_u2u_l, b_u2u, w_u2u_r); // 6
    k_bn_fin<<<1, 128>>>(bn_u_g, bn_u_b, 0, 512);        // 7
    k_xp<<<1024, 512>>>(gat_w, gat_as, gat_ad);          // 8
    k_gat_csr<<<1024, 256>>>(gat_b);                     // 9
    k_bn_fin<<<1, 128>>>(bn2_g, bn2_b, 256, 768);        // 10
    k_proj<<<1024, 256>>>(proj_w, proj_b, out);          // 11
}